// round 16
// baseline (speedup 1.0000x reference)
#include <cuda_runtime.h>
#include <cuda_fp16.h>
#include <cstdint>

// ---------------- problem constants ----------------
#define Nn    20000
#define N1c   6000
#define N2c   6000
#define Rr    3
#define Ee    200000
#define HIDc  128
#define NDIMc 64
#define D1c   64
#define D2c   32
#define Sc    2

// ---------------- device scratch ----------------
__device__ int   g_deg[Rr * Nn];      // zero at module load; re-zeroed at end of each DAG
__device__ int   g_cur[Rr * Nn];
__device__ int   g_ptr[Rr * (Nn + 1)];
__device__ int   g_csrc[Rr * Ee];
__device__ float g_h[(size_t)9 * Nn * 256];   // raw pool; fp16 views carved out of it
__device__ float g_el[720000];
__device__ float g_er[720000];
__device__ float g_hid[3 * Nn * D1c];         // slots 0,1 = he[s] (raw); slot 2 = hx

// ---------------- mma helpers ----------------
__device__ __forceinline__ uint32_t sptr(const void* p) {
    return (uint32_t)__cvta_generic_to_shared(p);
}
__device__ __forceinline__ void ldsm_x4(uint32_t& r0, uint32_t& r1, uint32_t& r2, uint32_t& r3, uint32_t a) {
    asm volatile("ldmatrix.sync.aligned.m8n8.x4.shared.b16 {%0,%1,%2,%3}, [%4];"
                 : "=r"(r0), "=r"(r1), "=r"(r2), "=r"(r3) : "r"(a));
}
__device__ __forceinline__ void ldsm_x2(uint32_t& r0, uint32_t& r1, uint32_t a) {
    asm volatile("ldmatrix.sync.aligned.m8n8.x2.shared.b16 {%0,%1}, [%2];"
                 : "=r"(r0), "=r"(r1) : "r"(a));
}
__device__ __forceinline__ void mma_f16(float c[4], const uint32_t a[4], const uint32_t b[2]) {
    asm volatile("mma.sync.aligned.m16n8k16.row.col.f32.f16.f16.f32 "
                 "{%0,%1,%2,%3},{%4,%5,%6,%7},{%8,%9},{%0,%1,%2,%3};"
                 : "+f"(c[0]), "+f"(c[1]), "+f"(c[2]), "+f"(c[3])
                 : "r"(a[0]), "r"(a[1]), "r"(a[2]), "r"(a[3]), "r"(b[0]), "r"(b[1]));
}

// ---------------- CSR build ----------------
__global__ void k_zero_deg(const float* __restrict__ rk, float* __restrict__ out_rk) {
    int i = blockIdx.x * blockDim.x + threadIdx.x;
    if (i < Rr * Nn) g_deg[i] = 0;
    if (blockIdx.x == 0 && threadIdx.x < 32)
        out_rk[threadIdx.x] = __fdividef(1.f, 1.f + __expf(-rk[threadIdx.x]));
}

__global__ void k_hist(const int* __restrict__ dst) {
    int idx = blockIdx.x * blockDim.x + threadIdx.x;
    if (idx < Rr * Ee) {
        int r = idx / Ee;
        atomicAdd(&g_deg[r * Nn + dst[idx]], 1);
    }
}

__global__ void k_scan() {
    __shared__ int sums[32];
    __shared__ int carry_s;
    int r = blockIdx.x;
    int t = threadIdx.x;
    int lane = t & 31, warp = t >> 5;
    if (t == 0) carry_s = 0;
    __syncthreads();
    for (int base = 0; base < Nn; base += 1024) {
        int carry = carry_s;
        int i = base + t;
        int v = (i < Nn) ? g_deg[r * Nn + i] : 0;
        int inc = v;
#pragma unroll
        for (int off = 1; off < 32; off <<= 1) {
            int n = __shfl_up_sync(0xffffffffu, inc, off);
            if (lane >= off) inc += n;
        }
        if (lane == 31) sums[warp] = inc;
        __syncthreads();
        if (warp == 0) {
            int s = sums[lane];
#pragma unroll
            for (int off = 1; off < 32; off <<= 1) {
                int n = __shfl_up_sync(0xffffffffu, s, off);
                if (lane >= off) s += n;
            }
            sums[lane] = s;
        }
        __syncthreads();
        int woff = (warp > 0) ? sums[warp - 1] : 0;
        int total = carry + woff + inc;
        if (i < Nn) {
            g_ptr[r * (Nn + 1) + i] = total - v;
            g_cur[r * Nn + i]       = total - v;
        }
        __syncthreads();
        if (t == 1023) carry_s = total;
        __syncthreads();
    }
    if (t == 0) g_ptr[r * (Nn + 1) + Nn] = carry_s;
}

__global__ void k_scatter(const int* __restrict__ src, const int* __restrict__ dst) {
    int idx = blockIdx.x * blockDim.x + threadIdx.x;
    if (idx < Rr * Ee) {
        int r = idx / Ee;
        int d = dst[idx];
        int pos = atomicAdd(&g_cur[r * Nn + d], 1);
        g_csrc[(size_t)r * Ee + pos] = src[idx];
    }
}

// ---------------- fp16 m16n8k16 GEMM with fused el/er epilogue; OH -> fp16 C ----------------
// Aresid: optional residual added to A rows for inst<2 (mu-GEMM: A = he[s] + hx).
template<int BN, bool OH>
__global__ __launch_bounds__(256) void gemm_mma(
    const float* __restrict__ Abase, size_t strideAinst, int K,
    const float* __restrict__ B0, const float* __restrict__ B1, const float* __restrict__ B2,
    int HF, void* __restrict__ Cbase, int M,
    const float* __restrict__ al0, const float* __restrict__ al1, const float* __restrict__ al2,
    const float* __restrict__ ar0, const float* __restrict__ ar1, const float* __restrict__ ar2,
    float* __restrict__ el, float* __restrict__ er,
    const float* __restrict__ Aresid)
{
    constexpr int RSH = 20;                // uint32 per row: 16 data (32 halves) + 4 pad
    constexpr int WN = BN / 2;
    constexpr int NT = WN / 8;
    __shared__ __align__(16) uint32_t As[128 * RSH];
    __shared__ __align__(16) uint32_t Bs[BN * RSH];

    int z = blockIdx.z;
    int r = z % Rr, inst = z / Rr;
    const float* A  = Abase + (size_t)inst * strideAinst;
    const float* Bw = (inst == 0 ? B0 : (inst == 1 ? B1 : B2)) + (size_t)r * K * HF;
    const float* Ar = (Aresid && inst < 2) ? Aresid : nullptr;

    int t = threadIdx.x;
    int lane = t & 31, warp = t >> 5;
    int warp_m = warp & 3, warp_n = warp >> 2;
    int bm = blockIdx.x * 128, bn = blockIdx.y * BN;

    float c[2][NT][4];
#pragma unroll
    for (int mt = 0; mt < 2; mt++)
#pragma unroll
        for (int nt = 0; nt < NT; nt++)
#pragma unroll
            for (int q = 0; q < 4; q++) c[mt][nt][q] = 0.f;

    for (int k0 = 0; k0 < K; k0 += 32) {
#pragma unroll
        for (int p = 0; p < 4; p++) {
            int fid = p * 256 + t;
            int row = fid >> 3, g = fid & 7;
            float4 v = make_float4(0.f, 0.f, 0.f, 0.f);
            if (bm + row < M) {
                v = *reinterpret_cast<const float4*>(A + (size_t)(bm + row) * K + k0 + g * 4);
                if (Ar) {
                    float4 rv = *reinterpret_cast<const float4*>(Ar + (size_t)(bm + row) * K + k0 + g * 4);
                    v.x += rv.x; v.y += rv.y; v.z += rv.z; v.w += rv.w;
                }
            }
            __half2 h01 = __floats2half2_rn(v.x, v.y);
            __half2 h23 = __floats2half2_rn(v.z, v.w);
            uint32_t* d = &As[row * RSH + g * 2];
            d[0] = *reinterpret_cast<uint32_t*>(&h01);
            d[1] = *reinterpret_cast<uint32_t*>(&h23);
        }
        {
            __half* Bh = reinterpret_cast<__half*>(Bs);
#pragma unroll
            for (int p = 0; p < BN / 32; p++) {
                int fid = p * 256 + t;
                int k = fid / (BN / 4), n = (fid % (BN / 4)) * 4;
                float4 v = *reinterpret_cast<const float4*>(Bw + (size_t)(k0 + k) * HF + bn + n);
                Bh[(n + 0) * (2 * RSH) + k] = __float2half_rn(v.x);
                Bh[(n + 1) * (2 * RSH) + k] = __float2half_rn(v.y);
                Bh[(n + 2) * (2 * RSH) + k] = __float2half_rn(v.z);
                Bh[(n + 3) * (2 * RSH) + k] = __float2half_rn(v.w);
            }
        }
        __syncthreads();
#pragma unroll
        for (int ks = 0; ks < 2; ks++) {
            uint32_t a[2][4];
#pragma unroll
            for (int mt = 0; mt < 2; mt++) {
                int rr = warp_m * 32 + mt * 16 + (lane & 7) + ((lane >> 3) & 1) * 8;
                int gg = ks * 2 + (lane >> 4);
                ldsm_x4(a[mt][0], a[mt][1], a[mt][2], a[mt][3], sptr(&As[rr * RSH + gg * 4]));
            }
            uint32_t b[NT][2];
#pragma unroll
            for (int nt = 0; nt < NT; nt++) {
                int rB = warp_n * WN + nt * 8 + (lane & 7);
                int gB = ks * 2 + ((lane >> 3) & 1);
                ldsm_x2(b[nt][0], b[nt][1], sptr(&Bs[rB * RSH + gB * 4]));
            }
#pragma unroll
            for (int mt = 0; mt < 2; mt++)
#pragma unroll
                for (int nt = 0; nt < NT; nt++) mma_f16(c[mt][nt], a[mt], b[nt]);
        }
        __syncthreads();
    }

    // ---- store C (fp32 or fp16) ----
#pragma unroll
    for (int mt = 0; mt < 2; mt++)
#pragma unroll
        for (int nt = 0; nt < NT; nt++) {
            int row0 = bm + warp_m * 32 + mt * 16 + (lane >> 2);
            int col  = bn + warp_n * WN + nt * 8 + (lane & 3) * 2;
            if (OH) {
                __half* C = (__half*)Cbase + (size_t)z * Nn * HF;
                if (row0 < M)
                    *reinterpret_cast<__half2*>(C + (size_t)row0 * HF + col) =
                        __float22half2_rn(make_float2(c[mt][nt][0], c[mt][nt][1]));
                if (row0 + 8 < M)
                    *reinterpret_cast<__half2*>(C + (size_t)(row0 + 8) * HF + col) =
                        __float22half2_rn(make_float2(c[mt][nt][2], c[mt][nt][3]));
            } else {
                float* C = (float*)Cbase + (size_t)z * Nn * HF;
                if (row0 < M)
                    *reinterpret_cast<float2*>(C + (size_t)row0 * HF + col) = make_float2(c[mt][nt][0], c[mt][nt][1]);
                if (row0 + 8 < M)
                    *reinterpret_cast<float2*>(C + (size_t)(row0 + 8) * HF + col) = make_float2(c[mt][nt][2], c[mt][nt][3]);
            }
        }

    // ---- fused el/er epilogue ----
    {
        int H = HF / WN;
        int head = bn / WN + warp_n;
        const float* alsel = (inst == 0 ? al0 : (inst == 1 ? al1 : al2));
        const float* arsel = (inst == 0 ? ar0 : (inst == 1 ? ar1 : ar2));
        const float* alp = alsel + (size_t)r * HF + bn + warp_n * WN;
        const float* arp = arsel + (size_t)r * HF + bn + warp_n * WN;
        float sl[2][2] = {{0.f, 0.f}, {0.f, 0.f}};
        float sr[2][2] = {{0.f, 0.f}, {0.f, 0.f}};
#pragma unroll
        for (int nt = 0; nt < NT; nt++) {
            int f0 = nt * 8 + (lane & 3) * 2;
            float a0 = alp[f0], a1 = alp[f0 + 1];
            float b0 = arp[f0], b1 = arp[f0 + 1];
#pragma unroll
            for (int mt = 0; mt < 2; mt++) {
                sl[mt][0] += c[mt][nt][0] * a0 + c[mt][nt][1] * a1;
                sl[mt][1] += c[mt][nt][2] * a0 + c[mt][nt][3] * a1;
                sr[mt][0] += c[mt][nt][0] * b0 + c[mt][nt][1] * b1;
                sr[mt][1] += c[mt][nt][2] * b0 + c[mt][nt][3] * b1;
            }
        }
#pragma unroll
        for (int off = 1; off < 4; off <<= 1)
#pragma unroll
            for (int mt = 0; mt < 2; mt++)
#pragma unroll
                for (int hf = 0; hf < 2; hf++) {
                    sl[mt][hf] += __shfl_xor_sync(0xffffffffu, sl[mt][hf], off);
                    sr[mt][hf] += __shfl_xor_sync(0xffffffffu, sr[mt][hf], off);
                }
        if ((lane & 3) == 0) {
#pragma unroll
            for (int mt = 0; mt < 2; mt++)
#pragma unroll
                for (int hf = 0; hf < 2; hf++) {
                    int row = bm + warp_m * 32 + mt * 16 + (lane >> 2) + 8 * hf;
                    if (row < M) {
                        size_t idx = ((size_t)z * Nn + row) * H + head;
                        el[idx] = sl[mt][hf];
                        er[idx] = sr[mt][hf];
                    }
                }
        }
    }
}

// ---------------- attention: warp per dst node, SINGLE edge sweep ----------------
template <int H, int F, bool RELU>
__global__ void k_attn(const __half* __restrict__ hb, const float* __restrict__ elb,
                       const float* __restrict__ erb, float* __restrict__ outb,
                       long long outStride, int instBase,
                       __half* __restrict__ out16b)
{
    constexpr int HF = H * F, PL = HF / 32, LPH = 32 / H;
    int inst = blockIdx.y + instBase;
    const float* el  = elb + (size_t)inst * Rr * Nn * H;
    const float* er  = erb + (size_t)inst * Rr * Nn * H;
    float* out = outb + (size_t)blockIdx.y * outStride;
    __half* out16 = out16b ? out16b + (size_t)blockIdx.y * outStride : nullptr;

    int w    = (blockIdx.x * blockDim.x + threadIdx.x) >> 5;
    int lane = threadIdx.x & 31;
    if (w >= Nn) return;
    const int i    = w;
    const int hidx = (lane * PL) / F;

    float af[PL];
#pragma unroll
    for (int k = 0; k < PL; k++) af[k] = 0.f;

    for (int r = 0; r < Rr; r++) {
        int s0 = g_ptr[r * (Nn + 1) + i];
        int s1 = g_ptr[r * (Nn + 1) + i + 1];
        if (s0 == s1) continue;
        float ei = er[(size_t)(r * Nn + i) * H + hidx];

        float num[PL];
#pragma unroll
        for (int k = 0; k < PL; k++) num[k] = 0.f;
        float den = 0.f;

        for (int j = s0; j < s1; j++) {
            int sn = g_csrc[(size_t)r * Ee + j];
            float e = el[(size_t)(r * Nn + sn) * H + hidx] + ei;
            e = (e > 0.f) ? e : 0.2f * e;
            float wgt = __expf(e);
            den += wgt;
            const __half* hrow = hb +
                ((size_t)inst * Rr * Nn + (size_t)r * Nn + sn) * HF + lane * PL;
            if (PL == 8) {
                uint4 raw = *reinterpret_cast<const uint4*>(hrow);
                float2 f0 = __half22float2(*reinterpret_cast<__half2*>(&raw.x));
                float2 f1 = __half22float2(*reinterpret_cast<__half2*>(&raw.y));
                float2 f2 = __half22float2(*reinterpret_cast<__half2*>(&raw.z));
                float2 f3 = __half22float2(*reinterpret_cast<__half2*>(&raw.w));
                num[0] = fmaf(wgt, f0.x, num[0]); num[1 % PL] = fmaf(wgt, f0.y, num[1 % PL]);
                num[2 % PL] = fmaf(wgt, f1.x, num[2 % PL]); num[3 % PL] = fmaf(wgt, f1.y, num[3 % PL]);
                num[4 % PL] = fmaf(wgt, f2.x, num[4 % PL]); num[5 % PL] = fmaf(wgt, f2.y, num[5 % PL]);
                num[6 % PL] = fmaf(wgt, f3.x, num[6 % PL]); num[7 % PL] = fmaf(wgt, f3.y, num[7 % PL]);
            } else {
                uint32_t raw = *reinterpret_cast<const uint32_t*>(hrow);
                float2 f0 = __half22float2(*reinterpret_cast<__half2*>(&raw));
                num[0] = fmaf(wgt, f0.x, num[0]); num[1 % PL] = fmaf(wgt, f0.y, num[1 % PL]);
            }
        }

        float inv = 1.f / (den + 1e-16f);
#pragma unroll
        for (int k = 0; k < PL; k++) af[k] = fmaf(num[k], inv, af[k]);
    }

#pragma unroll
    for (int k = 0; k < PL; k++) {
        float v = af[k];
#pragma unroll
        for (int off = LPH; off < 32; off <<= 1)
            v += __shfl_xor_sync(0xffffffffu, v, off);
        v *= (1.0f / H);
        if (RELU) v = fmaxf(v, 0.f);
        if (lane < LPH) {
            int idx = i * F + lane * PL + k;
            out[idx] = v;
            if (out16) out16[idx] = __float2half_rn(v);
        }
    }
}

// ---------------- misc ----------------
__device__ __forceinline__ float sigf(float x) {
    return __fdividef(1.f, 1.f + __expf(-x));
}

// ---------------- adj = mean_s sigmoid(z1[s] @ z2[s]^T), fp16 mma, 64x64 tile ----------------
__global__ __launch_bounds__(256) void k_adj_mma(const __half* __restrict__ mu16, float* __restrict__ adj)
{
    constexpr int RSH = 20;
    __shared__ __align__(16) uint32_t Z1s[Sc][64 * RSH];
    __shared__ __align__(16) uint32_t Z2s[Sc][64 * RSH];
    int t = threadIdx.x;
    int lane = t & 31, warp = t >> 5;
    int warp_m = warp & 1, warp_n = warp >> 1;   // 2m x 4n
    int bi = blockIdx.x * 64, bj = blockIdx.y * 64;

    int row = t >> 2, g = t & 3;
#pragma unroll
    for (int s = 0; s < Sc; s++) {
        uint4 v = make_uint4(0, 0, 0, 0);
        if (bi + row < N1c)
            v = *reinterpret_cast<const uint4*>(mu16 + ((size_t)s * Nn + bi + row) * 32 + g * 8);
        *reinterpret_cast<uint4*>(&Z1s[s][row * RSH + g * 4]) = v;
        v = make_uint4(0, 0, 0, 0);
        if (bj + row < N2c)
            v = *reinterpret_cast<const uint4*>(mu16 + ((size_t)s * Nn + N1c + bj + row) * 32 + g * 8);
        *reinterpret_cast<uint4*>(&Z2s[s][row * RSH + g * 4]) = v;
    }
    __syncthreads();

    float c[Sc][2][2][4];
#pragma unroll
    for (int s = 0; s < Sc; s++)
#pragma unroll
        for (int mt = 0; mt < 2; mt++)
#pragma unroll
            for (int nt = 0; nt < 2; nt++)
#pragma unroll
                for (int q = 0; q < 4; q++) c[s][mt][nt][q] = 0.f;

#pragma unroll
    for (int ks = 0; ks < 2; ks++) {
#pragma unroll
        for (int s = 0; s < Sc; s++) {
            uint32_t a[2][4];
#pragma unroll
            for (int mt = 0; mt < 2; mt++) {
                int rr = warp_m * 32 + mt * 16 + (lane & 7) + ((lane >> 3) & 1) * 8;
                int gg = ks * 2 + (lane >> 4);
                ldsm_x4(a[mt][0], a[mt][1], a[mt][2], a[mt][3], sptr(&Z1s[s][rr * RSH + gg * 4]));
            }
            uint32_t b[2][2];
#pragma unroll
            for (int nt = 0; nt < 2; nt++) {
                int rB = warp_n * 16 + nt * 8 + (lane & 7);
                int gB = ks * 2 + ((lane >> 3) & 1);
                ldsm_x2(b[nt][0], b[nt][1], sptr(&Z2s[s][rB * RSH + gB * 4]));
            }
#pragma unroll
            for (int mt = 0; mt < 2; mt++)
#pragma unroll
                for (int nt = 0; nt < 2; nt++) mma_f16(c[s][mt][nt], a[mt], b[nt]);
        }
    }

#pragma unroll
    for (int mt = 0; mt < 2; mt++)
#pragma unroll
        for (int nt = 0; nt < 2; nt++) {
            int row0 = bi + warp_m * 32 + mt * 16 + (lane >> 2);
            int col  = bj + warp_n * 16 + nt * 8 + (lane & 3) * 2;
            if (col >= N2c) continue;
            if (row0 < N1c) {
                float2 v = make_float2(0.5f * (sigf(c[0][mt][nt][0]) + sigf(c[1][mt][nt][0])),
                                       0.5f * (sigf(c[0][mt][nt][1]) + sigf(c[1][mt][nt][1])));
                *reinterpret_cast<float2*>(adj + (size_t)row0 * N2c + col) = v;
            }
            if (row0 + 8 < N1c) {
                float2 v = make_float2(0.5f * (sigf(c[0][mt][nt][2]) + sigf(c[1][mt][nt][2])),
                                       0.5f * (sigf(c[0][mt][nt][3]) + sigf(c[1][mt][nt][3])));
                *reinterpret_cast<float2*>(adj + (size_t)(row0 + 8) * N2c + col) = v;
            }
        }
}

// ---------------- host-side orchestration (fork-join stream overlap) ----------------
extern "C" void kernel_launch(void* const* d_in, const int* in_sizes, int n_in,
                              void* d_out, int out_size)
{
    (void)in_sizes; (void)n_in; (void)out_size;
    const float* x     = (const float*)d_in[0];
    const float* noise = (const float*)d_in[1];
    const float* W1    = (const float*)d_in[2];
    const float* al1   = (const float*)d_in[3];
    const float* ar1   = (const float*)d_in[4];
    const float* We    = (const float*)d_in[5];
    const float* ale   = (const float*)d_in[6];
    const float* are   = (const float*)d_in[7];
    const float* W2    = (const float*)d_in[8];
    const float* al2   = (const float*)d_in[9];
    const float* ar2   = (const float*)d_in[10];
    const float* W3    = (const float*)d_in[11];
    const float* al3   = (const float*)d_in[12];
    const float* ar3   = (const float*)d_in[13];
    const float* rk    = (const float*)d_in[14];
    const int*   src   = (const int*)d_in[15];
    const int*   dst   = (const int*)d_in[16];

    float* out     = (float*)d_out;
    float* out_adj = out;
    float* out_mu  = out + (size_t)N1c * N2c;
    float* out_lv  = out_mu + (size_t)Sc * Nn * D2c;
    float* out_rk  = out_lv + (size_t)Nn * D2c;

    float *hbuf, *elbuf, *erbuf, *hid;
    cudaGetSymbolAddress((void**)&hbuf,  g_h);
    cudaGetSymbolAddress((void**)&elbuf, g_el);
    cudaGetSymbolAddress((void**)&erbuf, g_er);
    cudaGetSymbolAddress((void**)&hid,   g_hid);
    float* hx = hid + (size_t)2 * Nn * D1c;
    __half* hh16 = (__half*)hbuf;
    __half* hh16_x = hh16 + (size_t)6 * Nn * 256;
    float* el_x = elbuf + (size_t)6 * Nn * 4;
    float* er_x = erbuf + (size_t)6 * Nn * 4;
    __half* mu16 = (__half*)(hbuf + (size_t)8 * Nn * 256);

    cudaStream_t sB, sC;
    cudaStreamCreateWithFlags(&sB, cudaStreamNonBlocking);
    cudaStreamCreateWithFlags(&sC, cudaStreamNonBlocking);
    cudaEvent_t e0, eCSR, eN, eB2;
    cudaEventCreateWithFlags(&e0,   cudaEventDisableTiming);
    cudaEventCreateWithFlags(&eCSR, cudaEventDisableTiming);
    cudaEventCreateWithFlags(&eN,   cudaEventDisableTiming);
    cudaEventCreateWithFlags(&eB2,  cudaEventDisableTiming);

    cudaEventRecord(e0, 0);
    cudaStreamWaitEvent(sB, e0, 0);
    cudaStreamWaitEvent(sC, e0, 0);

    // ---- stream B: CSR build. g_deg is zero at module load and re-zeroed at DAG end. ----
    k_hist<<<(Rr * Ee + 255) / 256, 256, 0, sB>>>(dst);
    k_scan<<<Rr, 1024, 0, sB>>>();
    k_scatter<<<(Rr * Ee + 255) / 256, 256, 0, sB>>>(src, dst);
    cudaEventRecord(eCSR, sB);
    // re-zero g_deg for next graph replay (+ rk2, independent output); joined via eB2 below
    k_zero_deg<<<(Rr * Nn + 255) / 256, 256, 0, sB>>>(rk, out_rk);
    cudaEventRecord(eB2, sB);

    // ---- stream C: noise GEMM (fp16 h, slots 0..5, insts 0,1) ----
    gemm_mma<128, true><<<dim3(157, 2, 6), 256, 0, sC>>>(noise, (size_t)Nn * NDIMc, NDIMc, We, We, We, 256, hh16, Nn,
                                                         ale, ale, ale, are, are, are, elbuf, erbuf, nullptr);
    cudaEventRecord(eN, sC);

    // ---- main: layer-x GEMM (fp16 h, slots 6..8, inst 2) ----
    gemm_mma<128, true><<<dim3(157, 2, 3), 256>>>(x, 0, HIDc, W1, W1, W1, 256, hh16_x, Nn,
                                                  al1, al1, al1, ar1, ar1, ar1, el_x, er_x, nullptr);
    cudaStreamWaitEvent(0, eCSR, 0);
    cudaStreamWaitEvent(0, eN, 0);
    // all three HF=256 attentions in ONE launch: insts 0,1 -> he[s]; inst 2 -> hx (all raw, no resid)
    k_attn<4, 64, true><<<dim3((Nn + 7) / 8, 3), 256>>>(hh16, elbuf, erbuf, hid, (long long)Nn * D1c, 0, nullptr);

    // ---- mu[0], mu[1], logvar: A = he[s] + hx for inst<2; A = hx for inst 2 ----
    gemm_mma<64, true><<<dim3(157, 1, 9), 256>>>(hid, (size_t)Nn * D1c, D1c, W2, W2, W3, 64, hh16, Nn,
                                                 al2, al2, al3, ar2, ar2, ar3, elbuf, erbuf, hx);
    k_attn<2, 32, false><<<dim3((Nn + 7) / 8, 3), 256>>>(hh16, elbuf, erbuf, out_mu, (long long)Nn * D2c, 0, mu16);

    // join stream B's trailing zero-deg work back into the capture origin
    cudaStreamWaitEvent(0, eB2, 0);

    // ---- adj = mean_s sigmoid(z1[s] @ z2[s]^T), fp16 mma ----
    k_adj_mma<<<dim3((N1c + 63) / 64, (N2c + 63) / 64), 256>>>(mu16, out_adj);

    cudaEventDestroy(e0);
    cudaEventDestroy(eCSR);
    cudaEventDestroy(eN);
    cudaEventDestroy(eB2);
    cudaStreamDestroy(sB);
    cudaStreamDestroy(sC);
}

// round 17
// speedup vs baseline: 1.0255x; 1.0255x over previous
#include <cuda_runtime.h>
#include <cuda_fp16.h>
#include <cstdint>

// ---------------- problem constants ----------------
#define Nn    20000
#define N1c   6000
#define N2c   6000
#define Rr    3
#define Ee    200000
#define HIDc  128
#define NDIMc 64
#define D1c   64
#define D2c   32
#define Sc    2

// ---------------- device scratch ----------------
__device__ int   g_deg[Rr * Nn];      // zero at module load; re-zeroed at end of each DAG
__device__ int   g_cur[Rr * Nn];
__device__ int   g_ptr[Rr * (Nn + 1)];
__device__ int   g_csrc[Rr * Ee];
__device__ float g_h[(size_t)9 * Nn * 256];   // raw pool; fp16 views carved out of it
__device__ float g_el[1080000];
__device__ float g_er[1080000];
__device__ float g_hid[3 * Nn * D1c];         // slots 0,1 = hidden1[s]; slot 2 = hx

// ---------------- mma helpers ----------------
__device__ __forceinline__ uint32_t sptr(const void* p) {
    return (uint32_t)__cvta_generic_to_shared(p);
}
__device__ __forceinline__ void ldsm_x4(uint32_t& r0, uint32_t& r1, uint32_t& r2, uint32_t& r3, uint32_t a) {
    asm volatile("ldmatrix.sync.aligned.m8n8.x4.shared.b16 {%0,%1,%2,%3}, [%4];"
                 : "=r"(r0), "=r"(r1), "=r"(r2), "=r"(r3) : "r"(a));
}
__device__ __forceinline__ void ldsm_x2(uint32_t& r0, uint32_t& r1, uint32_t a) {
    asm volatile("ldmatrix.sync.aligned.m8n8.x2.shared.b16 {%0,%1}, [%2];"
                 : "=r"(r0), "=r"(r1) : "r"(a));
}
__device__ __forceinline__ void mma_f16(float c[4], const uint32_t a[4], const uint32_t b[2]) {
    asm volatile("mma.sync.aligned.m16n8k16.row.col.f32.f16.f16.f32 "
                 "{%0,%1,%2,%3},{%4,%5,%6,%7},{%8,%9},{%0,%1,%2,%3};"
                 : "+f"(c[0]), "+f"(c[1]), "+f"(c[2]), "+f"(c[3])
                 : "r"(a[0]), "r"(a[1]), "r"(a[2]), "r"(a[3]), "r"(b[0]), "r"(b[1]));
}

// ---------------- CSR build ----------------
__global__ void k_zero_deg(const float* __restrict__ rk, float* __restrict__ out_rk) {
    int i = blockIdx.x * blockDim.x + threadIdx.x;
    if (i < Rr * Nn) g_deg[i] = 0;
    if (blockIdx.x == 0 && threadIdx.x < 32)
        out_rk[threadIdx.x] = __fdividef(1.f, 1.f + __expf(-rk[threadIdx.x]));
}

__global__ void k_hist(const int* __restrict__ dst) {
    int idx = blockIdx.x * blockDim.x + threadIdx.x;
    if (idx < Rr * Ee) {
        int r = idx / Ee;
        atomicAdd(&g_deg[r * Nn + dst[idx]], 1);
    }
}

__global__ void k_scan() {
    __shared__ int sums[32];
    __shared__ int carry_s;
    int r = blockIdx.x;
    int t = threadIdx.x;
    int lane = t & 31, warp = t >> 5;
    if (t == 0) carry_s = 0;
    __syncthreads();
    for (int base = 0; base < Nn; base += 1024) {
        int carry = carry_s;
        int i = base + t;
        int v = (i < Nn) ? g_deg[r * Nn + i] : 0;
        int inc = v;
#pragma unroll
        for (int off = 1; off < 32; off <<= 1) {
            int n = __shfl_up_sync(0xffffffffu, inc, off);
            if (lane >= off) inc += n;
        }
        if (lane == 31) sums[warp] = inc;
        __syncthreads();
        if (warp == 0) {
            int s = sums[lane];
#pragma unroll
            for (int off = 1; off < 32; off <<= 1) {
                int n = __shfl_up_sync(0xffffffffu, s, off);
                if (lane >= off) s += n;
            }
            sums[lane] = s;
        }
        __syncthreads();
        int woff = (warp > 0) ? sums[warp - 1] : 0;
        int total = carry + woff + inc;
        if (i < Nn) {
            g_ptr[r * (Nn + 1) + i] = total - v;
            g_cur[r * Nn + i]       = total - v;
        }
        __syncthreads();
        if (t == 1023) carry_s = total;
        __syncthreads();
    }
    if (t == 0) g_ptr[r * (Nn + 1) + Nn] = carry_s;
}

__global__ void k_scatter(const int* __restrict__ src, const int* __restrict__ dst) {
    int idx = blockIdx.x * blockDim.x + threadIdx.x;
    if (idx < Rr * Ee) {
        int r = idx / Ee;
        int d = dst[idx];
        int pos = atomicAdd(&g_cur[r * Nn + d], 1);
        g_csrc[(size_t)r * Ee + pos] = src[idx];
    }
}

// ---------------- fp16 m16n8k16 GEMM with fused el/er epilogue; OH -> fp16 C ----------------
template<int BN, bool OH>
__global__ __launch_bounds__(256) void gemm_mma(
    const float* __restrict__ Abase, size_t strideAinst, int K,
    const float* __restrict__ B0, const float* __restrict__ B1, const float* __restrict__ B2,
    int HF, void* __restrict__ Cbase, int M,
    const float* __restrict__ al0, const float* __restrict__ al1, const float* __restrict__ al2,
    const float* __restrict__ ar0, const float* __restrict__ ar1, const float* __restrict__ ar2,
    float* __restrict__ el, float* __restrict__ er)
{
    constexpr int RSH = 20;                // uint32 per row: 16 data (32 halves) + 4 pad
    constexpr int WN = BN / 2;
    constexpr int NT = WN / 8;
    __shared__ __align__(16) uint32_t As[128 * RSH];
    __shared__ __align__(16) uint32_t Bs[BN * RSH];

    int z = blockIdx.z;
    int r = z % Rr, inst = z / Rr;
    const float* A  = Abase + (size_t)inst * strideAinst;
    const float* Bw = (inst == 0 ? B0 : (inst == 1 ? B1 : B2)) + (size_t)r * K * HF;

    int t = threadIdx.x;
    int lane = t & 31, warp = t >> 5;
    int warp_m = warp & 3, warp_n = warp >> 2;
    int bm = blockIdx.x * 128, bn = blockIdx.y * BN;

    float c[2][NT][4];
#pragma unroll
    for (int mt = 0; mt < 2; mt++)
#pragma unroll
        for (int nt = 0; nt < NT; nt++)
#pragma unroll
            for (int q = 0; q < 4; q++) c[mt][nt][q] = 0.f;

    for (int k0 = 0; k0 < K; k0 += 32) {
#pragma unroll
        for (int p = 0; p < 4; p++) {
            int fid = p * 256 + t;
            int row = fid >> 3, g = fid & 7;
            float4 v = make_float4(0.f, 0.f, 0.f, 0.f);
            if (bm + row < M)
                v = *reinterpret_cast<const float4*>(A + (size_t)(bm + row) * K + k0 + g * 4);
            __half2 h01 = __floats2half2_rn(v.x, v.y);
            __half2 h23 = __floats2half2_rn(v.z, v.w);
            uint32_t* d = &As[row * RSH + g * 2];
            d[0] = *reinterpret_cast<uint32_t*>(&h01);
            d[1] = *reinterpret_cast<uint32_t*>(&h23);
        }
        {
            __half* Bh = reinterpret_cast<__half*>(Bs);
#pragma unroll
            for (int p = 0; p < BN / 32; p++) {
                int fid = p * 256 + t;
                int k = fid / (BN / 4), n = (fid % (BN / 4)) * 4;
                float4 v = *reinterpret_cast<const float4*>(Bw + (size_t)(k0 + k) * HF + bn + n);
                Bh[(n + 0) * (2 * RSH) + k] = __float2half_rn(v.x);
                Bh[(n + 1) * (2 * RSH) + k] = __float2half_rn(v.y);
                Bh[(n + 2) * (2 * RSH) + k] = __float2half_rn(v.z);
                Bh[(n + 3) * (2 * RSH) + k] = __float2half_rn(v.w);
            }
        }
        __syncthreads();
#pragma unroll
        for (int ks = 0; ks < 2; ks++) {
            uint32_t a[2][4];
#pragma unroll
            for (int mt = 0; mt < 2; mt++) {
                int rr = warp_m * 32 + mt * 16 + (lane & 7) + ((lane >> 3) & 1) * 8;
                int gg = ks * 2 + (lane >> 4);
                ldsm_x4(a[mt][0], a[mt][1], a[mt][2], a[mt][3], sptr(&As[rr * RSH + gg * 4]));
            }
            uint32_t b[NT][2];
#pragma unroll
            for (int nt = 0; nt < NT; nt++) {
                int rB = warp_n * WN + nt * 8 + (lane & 7);
                int gB = ks * 2 + ((lane >> 3) & 1);
                ldsm_x2(b[nt][0], b[nt][1], sptr(&Bs[rB * RSH + gB * 4]));
            }
#pragma unroll
            for (int mt = 0; mt < 2; mt++)
#pragma unroll
                for (int nt = 0; nt < NT; nt++) mma_f16(c[mt][nt], a[mt], b[nt]);
        }
        __syncthreads();
    }

    // ---- store C (fp32 or fp16) ----
#pragma unroll
    for (int mt = 0; mt < 2; mt++)
#pragma unroll
        for (int nt = 0; nt < NT; nt++) {
            int row0 = bm + warp_m * 32 + mt * 16 + (lane >> 2);
            int col  = bn + warp_n * WN + nt * 8 + (lane & 3) * 2;
            if (OH) {
                __half* C = (__half*)Cbase + (size_t)z * Nn * HF;
                if (row0 < M)
                    *reinterpret_cast<__half2*>(C + (size_t)row0 * HF + col) =
                        __float22half2_rn(make_float2(c[mt][nt][0], c[mt][nt][1]));
                if (row0 + 8 < M)
                    *reinterpret_cast<__half2*>(C + (size_t)(row0 + 8) * HF + col) =
                        __float22half2_rn(make_float2(c[mt][nt][2], c[mt][nt][3]));
            } else {
                float* C = (float*)Cbase + (size_t)z * Nn * HF;
                if (row0 < M)
                    *reinterpret_cast<float2*>(C + (size_t)row0 * HF + col) = make_float2(c[mt][nt][0], c[mt][nt][1]);
                if (row0 + 8 < M)
                    *reinterpret_cast<float2*>(C + (size_t)(row0 + 8) * HF + col) = make_float2(c[mt][nt][2], c[mt][nt][3]);
            }
        }

    // ---- fused el/er epilogue ----
    {
        int H = HF / WN;
        int head = bn / WN + warp_n;
        const float* alsel = (inst == 0 ? al0 : (inst == 1 ? al1 : al2));
        const float* arsel = (inst == 0 ? ar0 : (inst == 1 ? ar1 : ar2));
        const float* alp = alsel + (size_t)r * HF + bn + warp_n * WN;
        const float* arp = arsel + (size_t)r * HF + bn + warp_n * WN;
        float sl[2][2] = {{0.f, 0.f}, {0.f, 0.f}};
        float sr[2][2] = {{0.f, 0.f}, {0.f, 0.f}};
#pragma unroll
        for (int nt = 0; nt < NT; nt++) {
            int f0 = nt * 8 + (lane & 3) * 2;
            float a0 = alp[f0], a1 = alp[f0 + 1];
            float b0 = arp[f0], b1 = arp[f0 + 1];
#pragma unroll
            for (int mt = 0; mt < 2; mt++) {
                sl[mt][0] += c[mt][nt][0] * a0 + c[mt][nt][1] * a1;
                sl[mt][1] += c[mt][nt][2] * a0 + c[mt][nt][3] * a1;
                sr[mt][0] += c[mt][nt][0] * b0 + c[mt][nt][1] * b1;
                sr[mt][1] += c[mt][nt][2] * b0 + c[mt][nt][3] * b1;
            }
        }
#pragma unroll
        for (int off = 1; off < 4; off <<= 1)
#pragma unroll
            for (int mt = 0; mt < 2; mt++)
#pragma unroll
                for (int hf = 0; hf < 2; hf++) {
                    sl[mt][hf] += __shfl_xor_sync(0xffffffffu, sl[mt][hf], off);
                    sr[mt][hf] += __shfl_xor_sync(0xffffffffu, sr[mt][hf], off);
                }
        if ((lane & 3) == 0) {
#pragma unroll
            for (int mt = 0; mt < 2; mt++)
#pragma unroll
                for (int hf = 0; hf < 2; hf++) {
                    int row = bm + warp_m * 32 + mt * 16 + (lane >> 2) + 8 * hf;
                    if (row < M) {
                        size_t idx = ((size_t)z * Nn + row) * H + head;
                        el[idx] = sl[mt][hf];
                        er[idx] = sr[mt][hf];
                    }
                }
        }
    }
}

// ---------------- attention: warp per dst node, SINGLE edge sweep ----------------
template <int H, int F, bool RELU, bool ADD>
__global__ void k_attn(const __half* __restrict__ hb, const float* __restrict__ elb,
                       const float* __restrict__ erb, float* __restrict__ outb,
                       long long outStride, const float* __restrict__ resid, int instBase,
                       __half* __restrict__ out16b)
{
    constexpr int HF = H * F, PL = HF / 32, LPH = 32 / H;
    int inst = blockIdx.y + instBase;
    const float* el  = elb + (size_t)inst * Rr * Nn * H;
    const float* er  = erb + (size_t)inst * Rr * Nn * H;
    float* out = outb + (size_t)blockIdx.y * outStride;
    __half* out16 = out16b ? out16b + (size_t)blockIdx.y * outStride : nullptr;

    int w    = (blockIdx.x * blockDim.x + threadIdx.x) >> 5;
    int lane = threadIdx.x & 31;
    if (w >= Nn) return;
    const int i    = w;
    const int hidx = (lane * PL) / F;

    float af[PL];
#pragma unroll
    for (int k = 0; k < PL; k++) af[k] = 0.f;

    for (int r = 0; r < Rr; r++) {
        int s0 = g_ptr[r * (Nn + 1) + i];
        int s1 = g_ptr[r * (Nn + 1) + i + 1];
        if (s0 == s1) continue;
        float ei = er[(size_t)(r * Nn + i) * H + hidx];

        float num[PL];
#pragma unroll
        for (int k = 0; k < PL; k++) num[k] = 0.f;
        float den = 0.f;

        for (int j = s0; j < s1; j++) {
            int sn = g_csrc[(size_t)r * Ee + j];
            float e = el[(size_t)(r * Nn + sn) * H + hidx] + ei;
            e = (e > 0.f) ? e : 0.2f * e;
            float wgt = __expf(e);
            den += wgt;
            const __half* hrow = hb +
                ((size_t)inst * Rr * Nn + (size_t)r * Nn + sn) * HF + lane * PL;
            if (PL == 8) {
                uint4 raw = *reinterpret_cast<const uint4*>(hrow);
                float2 f0 = __half22float2(*reinterpret_cast<__half2*>(&raw.x));
                float2 f1 = __half22float2(*reinterpret_cast<__half2*>(&raw.y));
                float2 f2 = __half22float2(*reinterpret_cast<__half2*>(&raw.z));
                float2 f3 = __half22float2(*reinterpret_cast<__half2*>(&raw.w));
                num[0] = fmaf(wgt, f0.x, num[0]); num[1 % PL] = fmaf(wgt, f0.y, num[1 % PL]);
                num[2 % PL] = fmaf(wgt, f1.x, num[2 % PL]); num[3 % PL] = fmaf(wgt, f1.y, num[3 % PL]);
                num[4 % PL] = fmaf(wgt, f2.x, num[4 % PL]); num[5 % PL] = fmaf(wgt, f2.y, num[5 % PL]);
                num[6 % PL] = fmaf(wgt, f3.x, num[6 % PL]); num[7 % PL] = fmaf(wgt, f3.y, num[7 % PL]);
            } else {
                uint32_t raw = *reinterpret_cast<const uint32_t*>(hrow);
                float2 f0 = __half22float2(*reinterpret_cast<__half2*>(&raw));
                num[0] = fmaf(wgt, f0.x, num[0]); num[1 % PL] = fmaf(wgt, f0.y, num[1 % PL]);
            }
        }

        float inv = 1.f / (den + 1e-16f);
#pragma unroll
        for (int k = 0; k < PL; k++) af[k] = fmaf(num[k], inv, af[k]);
    }

#pragma unroll
    for (int k = 0; k < PL; k++) {
        float v = af[k];
#pragma unroll
        for (int off = LPH; off < 32; off <<= 1)
            v += __shfl_xor_sync(0xffffffffu, v, off);
        v *= (1.0f / H);
        if (RELU) v = fmaxf(v, 0.f);
        if (lane < LPH) {
            int idx = i * F + lane * PL + k;
            if (ADD) v += resid[idx];
            out[idx] = v;
            if (out16) out16[idx] = __float2half_rn(v);
        }
    }
}

// ---------------- misc ----------------
__device__ __forceinline__ float sigf(float x) {
    return __fdividef(1.f, 1.f + __expf(-x));
}

// ---------------- adj = mean_s sigmoid(z1[s] @ z2[s]^T), fp16 mma, 64x64 tile ----------------
__global__ __launch_bounds__(256) void k_adj_mma(const __half* __restrict__ mu16, float* __restrict__ adj)
{
    constexpr int RSH = 20;
    __shared__ __align__(16) uint32_t Z1s[Sc][64 * RSH];
    __shared__ __align__(16) uint32_t Z2s[Sc][64 * RSH];
    int t = threadIdx.x;
    int lane = t & 31, warp = t >> 5;
    int warp_m = warp & 1, warp_n = warp >> 1;   // 2m x 4n
    int bi = blockIdx.x * 64, bj = blockIdx.y * 64;

    int row = t >> 2, g = t & 3;
#pragma unroll
    for (int s = 0; s < Sc; s++) {
        uint4 v = make_uint4(0, 0, 0, 0);
        if (bi + row < N1c)
            v = *reinterpret_cast<const uint4*>(mu16 + ((size_t)s * Nn + bi + row) * 32 + g * 8);
        *reinterpret_cast<uint4*>(&Z1s[s][row * RSH + g * 4]) = v;
        v = make_uint4(0, 0, 0, 0);
        if (bj + row < N2c)
            v = *reinterpret_cast<const uint4*>(mu16 + ((size_t)s * Nn + N1c + bj + row) * 32 + g * 8);
        *reinterpret_cast<uint4*>(&Z2s[s][row * RSH + g * 4]) = v;
    }
    __syncthreads();

    float c[Sc][2][2][4];
#pragma unroll
    for (int s = 0; s < Sc; s++)
#pragma unroll
        for (int mt = 0; mt < 2; mt++)
#pragma unroll
            for (int nt = 0; nt < 2; nt++)
#pragma unroll
                for (int q = 0; q < 4; q++) c[s][mt][nt][q] = 0.f;

#pragma unroll
    for (int ks = 0; ks < 2; ks++) {
#pragma unroll
        for (int s = 0; s < Sc; s++) {
            uint32_t a[2][4];
#pragma unroll
            for (int mt = 0; mt < 2; mt++) {
                int rr = warp_m * 32 + mt * 16 + (lane & 7) + ((lane >> 3) & 1) * 8;
                int gg = ks * 2 + (lane >> 4);
                ldsm_x4(a[mt][0], a[mt][1], a[mt][2], a[mt][3], sptr(&Z1s[s][rr * RSH + gg * 4]));
            }
            uint32_t b[2][2];
#pragma unroll
            for (int nt = 0; nt < 2; nt++) {
                int rB = warp_n * 16 + nt * 8 + (lane & 7);
                int gB = ks * 2 + ((lane >> 3) & 1);
                ldsm_x2(b[nt][0], b[nt][1], sptr(&Z2s[s][rB * RSH + gB * 4]));
            }
#pragma unroll
            for (int mt = 0; mt < 2; mt++)
#pragma unroll
                for (int nt = 0; nt < 2; nt++) mma_f16(c[s][mt][nt], a[mt], b[nt]);
        }
    }

#pragma unroll
    for (int mt = 0; mt < 2; mt++)
#pragma unroll
        for (int nt = 0; nt < 2; nt++) {
            int row0 = bi + warp_m * 32 + mt * 16 + (lane >> 2);
            int col  = bj + warp_n * 16 + nt * 8 + (lane & 3) * 2;
            if (col >= N2c) continue;
            if (row0 < N1c) {
                float2 v = make_float2(0.5f * (sigf(c[0][mt][nt][0]) + sigf(c[1][mt][nt][0])),
                                       0.5f * (sigf(c[0][mt][nt][1]) + sigf(c[1][mt][nt][1])));
                *reinterpret_cast<float2*>(adj + (size_t)row0 * N2c + col) = v;
            }
            if (row0 + 8 < N1c) {
                float2 v = make_float2(0.5f * (sigf(c[0][mt][nt][2]) + sigf(c[1][mt][nt][2])),
                                       0.5f * (sigf(c[0][mt][nt][3]) + sigf(c[1][mt][nt][3])));
                *reinterpret_cast<float2*>(adj + (size_t)(row0 + 8) * N2c + col) = v;
            }
        }
}

// ---------------- host-side orchestration (fork-join stream overlap) ----------------
extern "C" void kernel_launch(void* const* d_in, const int* in_sizes, int n_in,
                              void* d_out, int out_size)
{
    (void)in_sizes; (void)n_in; (void)out_size;
    const float* x     = (const float*)d_in[0];
    const float* noise = (const float*)d_in[1];
    const float* W1    = (const float*)d_in[2];
    const float* al1   = (const float*)d_in[3];
    const float* ar1   = (const float*)d_in[4];
    const float* We    = (const float*)d_in[5];
    const float* ale   = (const float*)d_in[6];
    const float* are   = (const float*)d_in[7];
    const float* W2    = (const float*)d_in[8];
    const float* al2   = (const float*)d_in[9];
    const float* ar2   = (const float*)d_in[10];
    const float* W3    = (const float*)d_in[11];
    const float* al3   = (const float*)d_in[12];
    const float* ar3   = (const float*)d_in[13];
    const float* rk    = (const float*)d_in[14];
    const int*   src   = (const int*)d_in[15];
    const int*   dst   = (const int*)d_in[16];

    float* out     = (float*)d_out;
    float* out_adj = out;
    float* out_mu  = out + (size_t)N1c * N2c;
    float* out_lv  = out_mu + (size_t)Sc * Nn * D2c;
    float* out_rk  = out_lv + (size_t)Nn * D2c;

    float *hbuf, *elbuf, *erbuf, *hid;
    cudaGetSymbolAddress((void**)&hbuf,  g_h);
    cudaGetSymbolAddress((void**)&elbuf, g_el);
    cudaGetSymbolAddress((void**)&erbuf, g_er);
    cudaGetSymbolAddress((void**)&hid,   g_hid);
    float* hx = hid + (size_t)2 * Nn * D1c;
    // fp16 pool layout (halves): noise h 0..6e, layer-x h 6e..9e, mu h 9e..11.25e (e = Nn*256)
    __half* hh16   = (__half*)hbuf;
    __half* hh16_x = hh16 + (size_t)6 * Nn * 256;
    __half* hmu16  = hh16 + (size_t)9 * Nn * 256;
    // el/er: HF=256 phase uses [0, 720000); mu phase uses [720000, 1080000)
    float* el_x  = elbuf + (size_t)6 * Nn * 4;
    float* er_x  = erbuf + (size_t)6 * Nn * 4;
    float* elmu  = elbuf + 720000;
    float* ermu  = erbuf + 720000;
    float* elmu2 = elmu + (size_t)2 * Rr * Nn * 2;   // logvar (inst 2) region
    float* ermu2 = ermu + (size_t)2 * Rr * Nn * 2;
    __half* mu16 = (__half*)(hbuf + (size_t)8 * Nn * 256);   // 2 x Nn x 32 halves

    cudaStream_t sB, sC;
    cudaStreamCreateWithFlags(&sB, cudaStreamNonBlocking);
    cudaStreamCreateWithFlags(&sC, cudaStreamNonBlocking);
    cudaEvent_t e0, eCSR, eN, eB2, eX, eLV;
    cudaEventCreateWithFlags(&e0,   cudaEventDisableTiming);
    cudaEventCreateWithFlags(&eCSR, cudaEventDisableTiming);
    cudaEventCreateWithFlags(&eN,   cudaEventDisableTiming);
    cudaEventCreateWithFlags(&eB2,  cudaEventDisableTiming);
    cudaEventCreateWithFlags(&eX,   cudaEventDisableTiming);
    cudaEventCreateWithFlags(&eLV,  cudaEventDisableTiming);

    cudaEventRecord(e0, 0);
    cudaStreamWaitEvent(sB, e0, 0);
    cudaStreamWaitEvent(sC, e0, 0);

    // ---- stream B: CSR build (g_deg zero by invariant); re-zero at end ----
    k_hist<<<(Rr * Ee + 255) / 256, 256, 0, sB>>>(dst);
    k_scan<<<Rr, 1024, 0, sB>>>();
    k_scatter<<<(Rr * Ee + 255) / 256, 256, 0, sB>>>(src, dst);
    cudaEventRecord(eCSR, sB);
    k_zero_deg<<<(Rr * Nn + 255) / 256, 256, 0, sB>>>(rk, out_rk);
    cudaEventRecord(eB2, sB);

    // ---- stream C: noise GEMM (fp16 h, slots 0..5, insts 0,1) ----
    gemm_mma<128, true><<<dim3(157, 2, 6), 256, 0, sC>>>(noise, (size_t)Nn * NDIMc, NDIMc, We, We, We, 256, hh16, Nn,
                                                         ale, ale, ale, are, are, are, elbuf, erbuf);
    cudaEventRecord(eN, sC);

    // ---- main: layer-x GEMM (fp16 h, slots 6..8, inst 2) ----
    gemm_mma<128, true><<<dim3(157, 2, 3), 256>>>(x, 0, HIDc, W1, W1, W1, 256, hh16_x, Nn,
                                                  al1, al1, al1, ar1, ar1, ar1, el_x, er_x);
    cudaStreamWaitEvent(0, eCSR, 0);
    // attn_x (inst 2) -> hx; overlaps noise GEMM tail on sC
    k_attn<4, 64, true, false><<<dim3((Nn + 7) / 8, 1), 256>>>(hh16, elbuf, erbuf, hx, 0, nullptr, 2, nullptr);
    cudaEventRecord(eX, 0);

    // ---- stream C: logvar chain (depends only on hx), overlaps noise attention ----
    cudaStreamWaitEvent(sC, eX, 0);
    gemm_mma<64, true><<<dim3(157, 1, 3), 256, 0, sC>>>(hx, 0, D1c, W3, W3, W3, 64,
                                                        hmu16 + (size_t)6 * Nn * 64, Nn,
                                                        al3, al3, al3, ar3, ar3, ar3, elmu2, ermu2);
    k_attn<2, 32, false, false><<<dim3((Nn + 7) / 8, 1), 256, 0, sC>>>(hmu16, elmu, ermu, out_lv, 0, nullptr, 2, nullptr);
    cudaEventRecord(eLV, sC);

    // ---- main: noise attentions (ADD hx residual), batched y=2 ----
    cudaStreamWaitEvent(0, eN, 0);
    k_attn<4, 64, true, true><<<dim3((Nn + 7) / 8, 2), 256>>>(hh16, elbuf, erbuf, hid, (long long)Nn * D1c, hx, 0, nullptr);

    // ---- mu[0], mu[1]: GEMM on hidden1 (insts 0,1) + attention with fp16 mu copy ----
    gemm_mma<64, true><<<dim3(157, 1, 6), 256>>>(hid, (size_t)Nn * D1c, D1c, W2, W2, W2, 64, hmu16, Nn,
                                                 al2, al2, al2, ar2, ar2, ar2, elmu, ermu);
    k_attn<2, 32, false, false><<<dim3((Nn + 7) / 8, 2), 256>>>(hmu16, elmu, ermu, out_mu, (long long)Nn * D2c, nullptr, 0, mu16);

    // join side streams back into the capture origin
    cudaStreamWaitEvent(0, eLV, 0);
    cudaStreamWaitEvent(0, eB2, 0);

    // ---- adj = mean_s sigmoid(z1[s] @ z2[s]^T), fp16 mma ----
    k_adj_mma<<<dim3((N1c + 63) / 64, (N2c + 63) / 64), 256>>>(mu16, out_adj);

    cudaEventDestroy(e0);
    cudaEventDestroy(eCSR);
    cudaEventDestroy(eN);
    cudaEventDestroy(eB2);
    cudaEventDestroy(eX);
    cudaEventDestroy(eLV);
    cudaStreamDestroy(sB);
    cudaStreamDestroy(sC);
}